// round 14
// baseline (speedup 1.0000x reference)
#include <cuda_runtime.h>
#include <cstddef>

// ChamferLossSelf: B=4, N=4096, D=3.
// min_r ||q-r||^2 = |q|^2 + min_r (|r|^2 - 2 q.r); packed fma.rn.f32x2 inner loop.
// K1: self-NN slice partials (256 blocks) + init of cross atomic-min arrays.
// K2: 8 sort blocks + 256 cross blocks (RED.MIN results); the LAST cross block
//     per batch (atomic ticket) runs the tiny combine and writes out[b].
// (R12 structure; unroll kept at 8 — R13's regression attributed to unroll 16.)

constexpr int N_PTS = 4096;
constexpr int B_MAX = 4;
constexpr int THR   = 512;              // threads per block
constexpr int QPT   = 2;                // queries per thread
constexpr int QBLK  = THR * QPT;        // 1024 queries per NN block
constexpr int NCHNK = N_PTS / QBLK;     // 4 query chunks
constexpr int S     = 8;                // ref slices
constexpr int SLICE = N_PTS / S;        // 512 refs per slice
constexpr int SPAIR = SLICE / 2;        // 256 packed ref pairs
constexpr int GRP   = 16;               // pairs per mask-group
constexpr int NGRP  = SPAIR / GRP;      // 16 groups (== warps per block)
constexpr int NCROSS_B = 2 * NCHNK * S; // 64 cross units per batch
constexpr float BIG = 3.4e38f;
constexpr int   BIGI = 0x7F7FFFFF;      // FLT_MAX bit pattern

typedef unsigned long long ull;

__device__ float g_selfpart[2][B_MAX][S][N_PTS];   // self-NN slice partials
__device__ int   g_crossmin[2][B_MAX][N_PTS];      // cross-NN mins (int-view of float)
__device__ float g_sorted  [2][B_MAX][N_PTS];      // sorted self-NN dists

__device__ int d_cross_ctr[B_MAX];      // cross completion tickets (reset by consumer)
__device__ int d_sort_ctr [B_MAX];      // sorted arrays published   (reset by consumer)

__device__ __forceinline__ ull pack2(float a, float b) {
    ull r; asm("mov.b64 %0, {%1, %2};" : "=l"(r) : "f"(a), "f"(b)); return r;
}
__device__ __forceinline__ void unpack2(ull v, float& a, float& b) {
    asm("mov.b64 {%0, %1}, %2;" : "=f"(a), "=f"(b) : "l"(v));
}
__device__ __forceinline__ ull ffma2(ull a, ull b, ull c) {
    ull d; asm("fma.rn.f32x2 %0, %1, %2, %3;" : "=l"(d) : "l"(a), "l"(b), "l"(c)); return d;
}
__device__ __forceinline__ void fma2_min(float& b0, float& b1,
                                         ull nx, ull ny, ull nz,
                                         ull x2, ull y2, ull z2, ull w2) {
    asm("{\n\t"
        ".reg .b64 t;\n\t"
        ".reg .f32 lo, hi;\n\t"
        "fma.rn.f32x2 t, %4, %7, %8;\n\t"
        "fma.rn.f32x2 t, %3, %6, t;\n\t"
        "fma.rn.f32x2 t, %2, %5, t;\n\t"
        "mov.b64 {lo, hi}, t;\n\t"
        "min.f32 %0, %0, lo;\n\t"
        "min.f32 %1, %1, hi;\n\t"
        "}"
        : "+f"(b0), "+f"(b1)
        : "l"(nx), "l"(ny), "l"(nz), "l"(x2), "l"(y2), "l"(z2), "l"(w2));
}

struct QPack { ull nx, ny, nz; float qq; };

__device__ __forceinline__ QPack load_q(const float* __restrict__ q, int qi) {
    QPack o;
    const float x = q[qi * 3], y = q[qi * 3 + 1], z = q[qi * 3 + 2];
    o.qq = fmaf(x, x, fmaf(y, y, z * z));
    o.nx = pack2(-2.0f * x, -2.0f * x);
    o.ny = pack2(-2.0f * y, -2.0f * y);
    o.nz = pack2(-2.0f * z, -2.0f * z);
    return o;
}

// Stage slice refs as pairs: sXY[p]=(x0,x1,y0,y1), sZW[p]=(z0,z1,w0,w1), w=|r|^2.
__device__ __forceinline__ void stage_slice(const float* __restrict__ r, int rbase,
                                            float* sXY, float* sZW) {
    const int t = threadIdx.x;            // THR == SLICE: one ref per thread
    const float* rp = r + (size_t)(rbase + t) * 3;
    const float rx = rp[0], ry = rp[1], rz = rp[2];
    const float rw = fmaf(rx, rx, fmaf(ry, ry, rz * rz));
    const int p = t >> 1, l = t & 1;
    sXY[p * 4 + l]     = rx;
    sXY[p * 4 + 2 + l] = ry;
    sZW[p * 4 + l]     = rz;
    sZW[p * 4 + 2 + l] = rw;
}

// ---------------------------------------------------------------------------
// K1: self-NN partial mins. grid = 2*B*NCHNK*S (=256 for B=4).
// Also initializes g_crossmin to FLT_MAX bits (K1 completes before K2).
// ---------------------------------------------------------------------------
__global__ void __launch_bounds__(THR, 2) self_nn_kernel(const float* __restrict__ gts,
                                                         const float* __restrict__ preds,
                                                         int B) {
    __shared__ __align__(16) float sXY[SPAIR * 4];
    __shared__ __align__(16) float sZW[SPAIR * 4];

    const int tid = threadIdx.x;

    // Init cross atomic-min arrays: 2*B*N_PTS ints over 2*B*NCHNK*S blocks = 128/block.
    if (tid < 128)
        ((int*)g_crossmin)[blockIdx.x * 128 + tid] = BIGI;

    int u = blockIdx.x;
    const int s     = u % S;        u /= S;
    const int chunk = u % NCHNK;    u /= NCHNK;
    const int b     = u % B;        u /= B;
    const int pass  = u;            // 0: gts self, 1: preds self

    const float* p = (pass == 0 ? gts : preds) + (size_t)b * N_PTS * 3;
    const int qiA = chunk * QBLK + tid;
    const int qiB = qiA + THR;
    const int rbase = s * SLICE;

    const QPack A = load_q(p, qiA);
    const QPack Bq = load_q(p, qiB);
    stage_slice(p, rbase, sXY, sZW);
    __syncthreads();

    const ulonglong2* __restrict__ pXY = (const ulonglong2*)sXY;
    const ulonglong2* __restrict__ pZW = (const ulonglong2*)sZW;

    float bA0 = BIG, bA1 = BIG, bB0 = BIG, bB1 = BIG;

    const bool overlap = (rbase >= chunk * QBLK) && (rbase < chunk * QBLK + QBLK);

    if (!overlap) {
#pragma unroll 8
        for (int q = 0; q < SPAIR; ++q) {
            const ulonglong2 xy = pXY[q];
            const ulonglong2 zw = pZW[q];
            fma2_min(bA0, bA1, A.nx,  A.ny,  A.nz,  xy.x, xy.y, zw.x, zw.y);
            fma2_min(bB0, bB1, Bq.nx, Bq.ny, Bq.nz, xy.x, xy.y, zw.x, zw.y);
        }
    } else {
        // Diagonal ref index within slice == tid. Masked query: A if this
        // slice is the first half of the chunk, else B (uniform per block).
        const bool maskA = (rbase == chunk * QBLK);
        const int dpair = tid >> 1;
        const int pm0 = (tid & 1) ? -1 : dpair;
        const int pm1 = (tid & 1) ? dpair : -1;
        const int gd = tid >> 5;                  // group with diag (warp-uniform)

        for (int g = 0; g < NGRP; ++g) {
            const int base = g * GRP;
            if (g != gd) {
#pragma unroll
                for (int k = 0; k < GRP; ++k) {
                    const ulonglong2 xy = pXY[base + k];
                    const ulonglong2 zw = pZW[base + k];
                    fma2_min(bA0, bA1, A.nx,  A.ny,  A.nz,  xy.x, xy.y, zw.x, zw.y);
                    fma2_min(bB0, bB1, Bq.nx, Bq.ny, Bq.nz, xy.x, xy.y, zw.x, zw.y);
                }
            } else {
#pragma unroll
                for (int k = 0; k < GRP; ++k) {
                    const int p2 = base + k;
                    const ulonglong2 xy = pXY[p2];
                    const ulonglong2 zw = pZW[p2];
                    if (maskA) {
                        const ull dA = ffma2(A.nx, xy.x, ffma2(A.ny, xy.y, ffma2(A.nz, zw.x, zw.y)));
                        float e0, e1;
                        unpack2(dA, e0, e1);
                        if (p2 == pm0) e0 = BIG;
                        if (p2 == pm1) e1 = BIG;
                        bA0 = fminf(bA0, e0); bA1 = fminf(bA1, e1);
                        fma2_min(bB0, bB1, Bq.nx, Bq.ny, Bq.nz, xy.x, xy.y, zw.x, zw.y);
                    } else {
                        fma2_min(bA0, bA1, A.nx, A.ny, A.nz, xy.x, xy.y, zw.x, zw.y);
                        const ull dB = ffma2(Bq.nx, xy.x, ffma2(Bq.ny, xy.y, ffma2(Bq.nz, zw.x, zw.y)));
                        float e0, e1;
                        unpack2(dB, e0, e1);
                        if (p2 == pm0) e0 = BIG;
                        if (p2 == pm1) e1 = BIG;
                        bB0 = fminf(bB0, e0); bB1 = fminf(bB1, e1);
                    }
                }
            }
        }
    }

    g_selfpart[pass][b][s][qiA] = fminf(bA0, bA1) + A.qq;
    g_selfpart[pass][b][s][qiB] = fminf(bB0, bB1) + Bq.qq;
}

// ---------------------------------------------------------------------------
// Bitonic sort of 4096 floats in smem, 512 threads, 8 elems/thread.
// ---------------------------------------------------------------------------
__device__ __forceinline__ void bitonic_sort_4096(float* s) {
    const int t = threadIdx.x;
    float v[8];
#pragma unroll
    for (int w = 0; w < 8; ++w) v[w] = s[w * 512 + t];
#pragma unroll
    for (int k = 2; k <= 32; k <<= 1) {
#pragma unroll
        for (int j = k >> 1; j >= 1; j >>= 1) {
#pragma unroll
            for (int w = 0; w < 8; ++w) {
                const int i = w * 512 + t;
                const float pv = __shfl_xor_sync(0xffffffffu, v[w], j);
                const bool up    = ((i & k) == 0);
                const bool lower = ((t & j) == 0);
                v[w] = (lower == up) ? fminf(v[w], pv) : fmaxf(v[w], pv);
            }
        }
    }
#pragma unroll
    for (int w = 0; w < 8; ++w) s[w * 512 + t] = v[w];

    for (int k = 64; k <= 4096; k <<= 1) {
        for (int j = k >> 1; j >= 32; j >>= 1) {
            __syncthreads();
#pragma unroll
            for (int w = 0; w < 8; ++w) {
                const int i = w * 512 + t;
                if ((i & j) == 0) {
                    const int ix = i | j;
                    const float a = s[i], c = s[ix];
                    const bool up = ((i & k) == 0);
                    if ((a > c) == up) { s[i] = c; s[ix] = a; }
                }
            }
        }
        __syncthreads();
#pragma unroll
        for (int w = 0; w < 8; ++w) v[w] = s[w * 512 + t];
#pragma unroll
        for (int j = 16; j >= 1; j >>= 1) {
#pragma unroll
            for (int w = 0; w < 8; ++w) {
                const int i = w * 512 + t;
                const float pv = __shfl_xor_sync(0xffffffffu, v[w], j);
                const bool up    = ((i & k) == 0);
                const bool lower = ((t & j) == 0);
                v[w] = (lower == up) ? fminf(v[w], pv) : fmaxf(v[w], pv);
            }
        }
#pragma unroll
        for (int w = 0; w < 8; ++w) s[w * 512 + t] = v[w];
    }
    __syncthreads();
}

// ---------------------------------------------------------------------------
// K2 (fused): blocks [0, 2B) min-combine + sort one self array each, then
// signal sort_ctr. Blocks [2B, ...) cross-NN slices via RED.MIN; the last
// cross finisher per batch (ticket) waits for both sorts and combines.
// ---------------------------------------------------------------------------
__global__ void __launch_bounds__(THR, 2) fused_kernel(const float* __restrict__ gts,
                                                       const float* __restrict__ preds,
                                                       float* __restrict__ out,
                                                       int B) {
    __shared__ __align__(16) float pool[N_PTS];   // 16 KB (sort); cross uses 8 KB
    __shared__ int s_last;

    const int tid = threadIdx.x;

    if ((int)blockIdx.x < 2 * B) {
        const int arr = blockIdx.x & 1;
        const int b   = blockIdx.x >> 1;
        for (int i = tid; i < N_PTS; i += THR) {
            float m = g_selfpart[arr][b][0][i];
#pragma unroll
            for (int sp = 1; sp < S; ++sp) m = fminf(m, g_selfpart[arr][b][sp][i]);
            pool[i] = m;
        }
        __syncthreads();
        bitonic_sort_4096(pool);
        for (int i = tid; i < N_PTS; i += THR) g_sorted[arr][b][i] = pool[i];
        __syncthreads();
        if (tid == 0) {
            __threadfence();
            atomicAdd(&d_sort_ctr[b], 1);
        }
        return;
    }

    int u = blockIdx.x - 2 * B;
    const int s     = u % S;        u /= S;
    const int chunk = u % NCHNK;    u /= NCHNK;
    const int b     = u % B;        u /= B;
    const int pass  = u;            // 0: q=gts r=preds, 1: q=preds r=gts

    const float* q = (pass == 0 ? gts : preds) + (size_t)b * N_PTS * 3;
    const float* r = (pass == 0 ? preds : gts) + (size_t)b * N_PTS * 3;
    const int qiA = chunk * QBLK + tid;
    const int qiB = qiA + THR;

    float* sXY = pool;
    float* sZW = pool + SPAIR * 4;

    const QPack A = load_q(q, qiA);
    const QPack Bq = load_q(q, qiB);
    stage_slice(r, s * SLICE, sXY, sZW);
    __syncthreads();

    const ulonglong2* __restrict__ pXY = (const ulonglong2*)sXY;
    const ulonglong2* __restrict__ pZW = (const ulonglong2*)sZW;

    float bA0 = BIG, bA1 = BIG, bB0 = BIG, bB1 = BIG;
#pragma unroll 8
    for (int p = 0; p < SPAIR; ++p) {
        const ulonglong2 xy = pXY[p];
        const ulonglong2 zw = pZW[p];
        fma2_min(bA0, bA1, A.nx,  A.ny,  A.nz,  xy.x, xy.y, zw.x, zw.y);
        fma2_min(bB0, bB1, Bq.nx, Bq.ny, Bq.nz, xy.x, xy.y, zw.x, zw.y);
    }

    // Distances are >= 0 (up to rounding): int-view atomicMin == float min.
    atomicMin(&g_crossmin[pass][b][qiA], __float_as_int(fminf(bA0, bA1) + A.qq));
    atomicMin(&g_crossmin[pass][b][qiB], __float_as_int(fminf(bB0, bB1) + Bq.qq));

    // Ticket: last cross finisher of this batch performs the combine.
    if (tid == 0) {
        __threadfence();
        const int old = atomicAdd(&d_cross_ctr[b], 1);
        s_last = (old == NCROSS_B - 1);
    }
    __syncthreads();
    if (!s_last) return;

    if (tid == 0) {
        while (atomicAdd(&d_sort_ctr[b], 0) < 2) __nanosleep(64);
        d_sort_ctr[b]  = 0;          // reset for next graph replay
        d_cross_ctr[b] = 0;
    }
    __syncthreads();
    __threadfence();                 // acquire: peers' g_crossmin + g_sorted

    float acc = 0.0f;
    for (int i = tid; i < N_PTS; i += THR) {
        const float m0 = __int_as_float(g_crossmin[0][b][i]);
        const float m1 = __int_as_float(g_crossmin[1][b][i]);
        const float d  = g_sorted[0][b][i] - g_sorted[1][b][i];
        acc += m0 + m1;
        acc = fmaf(d, d, acc);
    }
#pragma unroll
    for (int o = 16; o; o >>= 1) acc += __shfl_xor_sync(0xffffffffu, acc, o);
    __syncthreads();                 // pool free for reuse
    if ((tid & 31) == 0) pool[tid >> 5] = acc;
    __syncthreads();
    if (tid == 0) {
        float sum = 0.0f;
#pragma unroll
        for (int w = 0; w < THR / 32; ++w) sum += pool[w];
        out[b] = sum;
    }
}

extern "C" void kernel_launch(void* const* d_in, const int* in_sizes, int n_in,
                              void* d_out, int out_size) {
    const float* gts   = (const float*)d_in[0];
    const float* preds = (const float*)d_in[1];
    float* out = (float*)d_out;
    const int B = in_sizes[0] / (N_PTS * 3);

    self_nn_kernel<<<2 * B * NCHNK * S, THR>>>(gts, preds, B);               // 256 blocks
    fused_kernel<<<2 * B + 2 * B * NCHNK * S, THR>>>(gts, preds, out, B);    // 264 blocks
}

// round 15
// speedup vs baseline: 1.0341x; 1.0341x over previous
#include <cuda_runtime.h>
#include <cstddef>

// ChamferLossSelf: B=4, N=4096, D=3.  (R12 champion, 58.1 us)
// min_r ||q-r||^2 = |q|^2 + min_r (|r|^2 - 2 q.r); packed fma.rn.f32x2 inner loop.
// K1: self-NN slice partials (256 blocks) + init of cross atomic-min arrays.
// K2: 8 sort blocks (hidden under cross) + 256 cross blocks (RED.MIN results).
// K3: tiny combine (reads 2 cross arrays + 2 sorted arrays).

constexpr int N_PTS = 4096;
constexpr int B_MAX = 4;
constexpr int THR   = 512;              // threads per block
constexpr int QPT   = 2;                // queries per thread
constexpr int QBLK  = THR * QPT;        // 1024 queries per NN block
constexpr int NCHNK = N_PTS / QBLK;     // 4 query chunks
constexpr int S     = 8;                // ref slices
constexpr int SLICE = N_PTS / S;        // 512 refs per slice
constexpr int SPAIR = SLICE / 2;        // 256 packed ref pairs
constexpr int GRP   = 16;               // pairs per mask-group
constexpr int NGRP  = SPAIR / GRP;      // 16 groups (== warps per block)
constexpr float BIG = 3.4e38f;
constexpr int   BIGI = 0x7F7FFFFF;      // FLT_MAX bit pattern

typedef unsigned long long ull;

__device__ float g_selfpart[2][B_MAX][S][N_PTS];   // self-NN slice partials
__device__ int   g_crossmin[2][B_MAX][N_PTS];      // cross-NN mins (int-view of float)
__device__ float g_sorted  [2][B_MAX][N_PTS];      // sorted self-NN dists

__device__ __forceinline__ ull pack2(float a, float b) {
    ull r; asm("mov.b64 %0, {%1, %2};" : "=l"(r) : "f"(a), "f"(b)); return r;
}
__device__ __forceinline__ void unpack2(ull v, float& a, float& b) {
    asm("mov.b64 {%0, %1}, %2;" : "=f"(a), "=f"(b) : "l"(v));
}
__device__ __forceinline__ ull ffma2(ull a, ull b, ull c) {
    ull d; asm("fma.rn.f32x2 %0, %1, %2, %3;" : "=l"(d) : "l"(a), "l"(b), "l"(c)); return d;
}
__device__ __forceinline__ void fma2_min(float& b0, float& b1,
                                         ull nx, ull ny, ull nz,
                                         ull x2, ull y2, ull z2, ull w2) {
    asm("{\n\t"
        ".reg .b64 t;\n\t"
        ".reg .f32 lo, hi;\n\t"
        "fma.rn.f32x2 t, %4, %7, %8;\n\t"
        "fma.rn.f32x2 t, %3, %6, t;\n\t"
        "fma.rn.f32x2 t, %2, %5, t;\n\t"
        "mov.b64 {lo, hi}, t;\n\t"
        "min.f32 %0, %0, lo;\n\t"
        "min.f32 %1, %1, hi;\n\t"
        "}"
        : "+f"(b0), "+f"(b1)
        : "l"(nx), "l"(ny), "l"(nz), "l"(x2), "l"(y2), "l"(z2), "l"(w2));
}

struct QPack { ull nx, ny, nz; float qq; };

__device__ __forceinline__ QPack load_q(const float* __restrict__ q, int qi) {
    QPack o;
    const float x = q[qi * 3], y = q[qi * 3 + 1], z = q[qi * 3 + 2];
    o.qq = fmaf(x, x, fmaf(y, y, z * z));
    o.nx = pack2(-2.0f * x, -2.0f * x);
    o.ny = pack2(-2.0f * y, -2.0f * y);
    o.nz = pack2(-2.0f * z, -2.0f * z);
    return o;
}

// Stage slice refs as pairs: sXY[p]=(x0,x1,y0,y1), sZW[p]=(z0,z1,w0,w1), w=|r|^2.
__device__ __forceinline__ void stage_slice(const float* __restrict__ r, int rbase,
                                            float* sXY, float* sZW) {
    const int t = threadIdx.x;            // THR == SLICE: one ref per thread
    const float* rp = r + (size_t)(rbase + t) * 3;
    const float rx = rp[0], ry = rp[1], rz = rp[2];
    const float rw = fmaf(rx, rx, fmaf(ry, ry, rz * rz));
    const int p = t >> 1, l = t & 1;
    sXY[p * 4 + l]     = rx;
    sXY[p * 4 + 2 + l] = ry;
    sZW[p * 4 + l]     = rz;
    sZW[p * 4 + 2 + l] = rw;
}

// ---------------------------------------------------------------------------
// K1: self-NN partial mins. grid = 2*B*NCHNK*S (=256 for B=4).
// Also initializes g_crossmin to FLT_MAX bits (K1 completes before K2).
// ---------------------------------------------------------------------------
__global__ void __launch_bounds__(THR, 2) self_nn_kernel(const float* __restrict__ gts,
                                                         const float* __restrict__ preds,
                                                         int B) {
    __shared__ __align__(16) float sXY[SPAIR * 4];
    __shared__ __align__(16) float sZW[SPAIR * 4];

    const int tid = threadIdx.x;

    // Init cross atomic-min arrays: 2*B*N_PTS ints over 2*B*NCHNK*S blocks = 128/block.
    if (tid < 128)
        ((int*)g_crossmin)[blockIdx.x * 128 + tid] = BIGI;

    int u = blockIdx.x;
    const int s     = u % S;        u /= S;
    const int chunk = u % NCHNK;    u /= NCHNK;
    const int b     = u % B;        u /= B;
    const int pass  = u;            // 0: gts self, 1: preds self

    const float* p = (pass == 0 ? gts : preds) + (size_t)b * N_PTS * 3;
    const int qiA = chunk * QBLK + tid;
    const int qiB = qiA + THR;
    const int rbase = s * SLICE;

    const QPack A = load_q(p, qiA);
    const QPack Bq = load_q(p, qiB);
    stage_slice(p, rbase, sXY, sZW);
    __syncthreads();

    const ulonglong2* __restrict__ pXY = (const ulonglong2*)sXY;
    const ulonglong2* __restrict__ pZW = (const ulonglong2*)sZW;

    float bA0 = BIG, bA1 = BIG, bB0 = BIG, bB1 = BIG;

    const bool overlap = (rbase >= chunk * QBLK) && (rbase < chunk * QBLK + QBLK);

    if (!overlap) {
#pragma unroll 8
        for (int q = 0; q < SPAIR; ++q) {
            const ulonglong2 xy = pXY[q];
            const ulonglong2 zw = pZW[q];
            fma2_min(bA0, bA1, A.nx,  A.ny,  A.nz,  xy.x, xy.y, zw.x, zw.y);
            fma2_min(bB0, bB1, Bq.nx, Bq.ny, Bq.nz, xy.x, xy.y, zw.x, zw.y);
        }
    } else {
        // Diagonal ref index within slice == tid. Masked query: A if this
        // slice is the first half of the chunk, else B (uniform per block).
        const bool maskA = (rbase == chunk * QBLK);
        const int dpair = tid >> 1;
        const int pm0 = (tid & 1) ? -1 : dpair;
        const int pm1 = (tid & 1) ? dpair : -1;
        const int gd = tid >> 5;                  // group with diag (warp-uniform)

        for (int g = 0; g < NGRP; ++g) {
            const int base = g * GRP;
            if (g != gd) {
#pragma unroll
                for (int k = 0; k < GRP; ++k) {
                    const ulonglong2 xy = pXY[base + k];
                    const ulonglong2 zw = pZW[base + k];
                    fma2_min(bA0, bA1, A.nx,  A.ny,  A.nz,  xy.x, xy.y, zw.x, zw.y);
                    fma2_min(bB0, bB1, Bq.nx, Bq.ny, Bq.nz, xy.x, xy.y, zw.x, zw.y);
                }
            } else {
#pragma unroll
                for (int k = 0; k < GRP; ++k) {
                    const int p2 = base + k;
                    const ulonglong2 xy = pXY[p2];
                    const ulonglong2 zw = pZW[p2];
                    if (maskA) {
                        const ull dA = ffma2(A.nx, xy.x, ffma2(A.ny, xy.y, ffma2(A.nz, zw.x, zw.y)));
                        float e0, e1;
                        unpack2(dA, e0, e1);
                        if (p2 == pm0) e0 = BIG;
                        if (p2 == pm1) e1 = BIG;
                        bA0 = fminf(bA0, e0); bA1 = fminf(bA1, e1);
                        fma2_min(bB0, bB1, Bq.nx, Bq.ny, Bq.nz, xy.x, xy.y, zw.x, zw.y);
                    } else {
                        fma2_min(bA0, bA1, A.nx, A.ny, A.nz, xy.x, xy.y, zw.x, zw.y);
                        const ull dB = ffma2(Bq.nx, xy.x, ffma2(Bq.ny, xy.y, ffma2(Bq.nz, zw.x, zw.y)));
                        float e0, e1;
                        unpack2(dB, e0, e1);
                        if (p2 == pm0) e0 = BIG;
                        if (p2 == pm1) e1 = BIG;
                        bB0 = fminf(bB0, e0); bB1 = fminf(bB1, e1);
                    }
                }
            }
        }
    }

    g_selfpart[pass][b][s][qiA] = fminf(bA0, bA1) + A.qq;
    g_selfpart[pass][b][s][qiB] = fminf(bB0, bB1) + Bq.qq;
}

// ---------------------------------------------------------------------------
// Bitonic sort of 4096 floats in smem, 512 threads, 8 elems/thread.
// ---------------------------------------------------------------------------
__device__ __forceinline__ void bitonic_sort_4096(float* s) {
    const int t = threadIdx.x;
    float v[8];
#pragma unroll
    for (int w = 0; w < 8; ++w) v[w] = s[w * 512 + t];
#pragma unroll
    for (int k = 2; k <= 32; k <<= 1) {
#pragma unroll
        for (int j = k >> 1; j >= 1; j >>= 1) {
#pragma unroll
            for (int w = 0; w < 8; ++w) {
                const int i = w * 512 + t;
                const float pv = __shfl_xor_sync(0xffffffffu, v[w], j);
                const bool up    = ((i & k) == 0);
                const bool lower = ((t & j) == 0);
                v[w] = (lower == up) ? fminf(v[w], pv) : fmaxf(v[w], pv);
            }
        }
    }
#pragma unroll
    for (int w = 0; w < 8; ++w) s[w * 512 + t] = v[w];

    for (int k = 64; k <= 4096; k <<= 1) {
        for (int j = k >> 1; j >= 32; j >>= 1) {
            __syncthreads();
#pragma unroll
            for (int w = 0; w < 8; ++w) {
                const int i = w * 512 + t;
                if ((i & j) == 0) {
                    const int ix = i | j;
                    const float a = s[i], c = s[ix];
                    const bool up = ((i & k) == 0);
                    if ((a > c) == up) { s[i] = c; s[ix] = a; }
                }
            }
        }
        __syncthreads();
#pragma unroll
        for (int w = 0; w < 8; ++w) v[w] = s[w * 512 + t];
#pragma unroll
        for (int j = 16; j >= 1; j >>= 1) {
#pragma unroll
            for (int w = 0; w < 8; ++w) {
                const int i = w * 512 + t;
                const float pv = __shfl_xor_sync(0xffffffffu, v[w], j);
                const bool up    = ((i & k) == 0);
                const bool lower = ((t & j) == 0);
                v[w] = (lower == up) ? fminf(v[w], pv) : fmaxf(v[w], pv);
            }
        }
#pragma unroll
        for (int w = 0; w < 8; ++w) s[w * 512 + t] = v[w];
    }
    __syncthreads();
}

// ---------------------------------------------------------------------------
// K2 (fused): blocks [0, 2B) min-combine + sort one self array each;
// blocks [2B, ...) cross-NN slices, results via RED.MIN into g_crossmin.
// ---------------------------------------------------------------------------
__global__ void __launch_bounds__(THR, 2) fused_kernel(const float* __restrict__ gts,
                                                       const float* __restrict__ preds,
                                                       int B) {
    __shared__ __align__(16) float pool[N_PTS];   // 16 KB (sort); cross uses 8 KB

    const int tid = threadIdx.x;

    if ((int)blockIdx.x < 2 * B) {
        const int arr = blockIdx.x & 1;
        const int b   = blockIdx.x >> 1;
        for (int i = tid; i < N_PTS; i += THR) {
            float m = g_selfpart[arr][b][0][i];
#pragma unroll
            for (int sp = 1; sp < S; ++sp) m = fminf(m, g_selfpart[arr][b][sp][i]);
            pool[i] = m;
        }
        __syncthreads();
        bitonic_sort_4096(pool);
        for (int i = tid; i < N_PTS; i += THR) g_sorted[arr][b][i] = pool[i];
        return;
    }

    int u = blockIdx.x - 2 * B;
    const int s     = u % S;        u /= S;
    const int chunk = u % NCHNK;    u /= NCHNK;
    const int b     = u % B;        u /= B;
    const int pass  = u;            // 0: q=gts r=preds, 1: q=preds r=gts

    const float* q = (pass == 0 ? gts : preds) + (size_t)b * N_PTS * 3;
    const float* r = (pass == 0 ? preds : gts) + (size_t)b * N_PTS * 3;
    const int qiA = chunk * QBLK + tid;
    const int qiB = qiA + THR;

    float* sXY = pool;
    float* sZW = pool + SPAIR * 4;

    const QPack A = load_q(q, qiA);
    const QPack Bq = load_q(q, qiB);
    stage_slice(r, s * SLICE, sXY, sZW);
    __syncthreads();

    const ulonglong2* __restrict__ pXY = (const ulonglong2*)sXY;
    const ulonglong2* __restrict__ pZW = (const ulonglong2*)sZW;

    float bA0 = BIG, bA1 = BIG, bB0 = BIG, bB1 = BIG;
#pragma unroll 8
    for (int p = 0; p < SPAIR; ++p) {
        const ulonglong2 xy = pXY[p];
        const ulonglong2 zw = pZW[p];
        fma2_min(bA0, bA1, A.nx,  A.ny,  A.nz,  xy.x, xy.y, zw.x, zw.y);
        fma2_min(bB0, bB1, Bq.nx, Bq.ny, Bq.nz, xy.x, xy.y, zw.x, zw.y);
    }

    // Distances are >= 0 (up to rounding): int-view atomicMin == float min.
    atomicMin(&g_crossmin[pass][b][qiA], __float_as_int(fminf(bA0, bA1) + A.qq));
    atomicMin(&g_crossmin[pass][b][qiB], __float_as_int(fminf(bB0, bB1) + Bq.qq));
}

// ---------------------------------------------------------------------------
// K3: per-batch combine. Reads only 2 cross arrays + 2 sorted arrays.
// ---------------------------------------------------------------------------
__global__ void __launch_bounds__(THR) combine_kernel(float* __restrict__ out) {
    const int b   = blockIdx.x;
    const int tid = threadIdx.x;

    float acc = 0.0f;
    for (int i = tid; i < N_PTS; i += THR) {
        const float m0 = __int_as_float(g_crossmin[0][b][i]);
        const float m1 = __int_as_float(g_crossmin[1][b][i]);
        const float d  = g_sorted[0][b][i] - g_sorted[1][b][i];
        acc += m0 + m1;
        acc = fmaf(d, d, acc);
    }

    __shared__ float red[16];
#pragma unroll
    for (int o = 16; o; o >>= 1) acc += __shfl_xor_sync(0xffffffffu, acc, o);
    if ((tid & 31) == 0) red[tid >> 5] = acc;
    __syncthreads();
    if (tid == 0) {
        float sum = 0.0f;
#pragma unroll
        for (int w = 0; w < 16; ++w) sum += red[w];
        out[b] = sum;
    }
}

extern "C" void kernel_launch(void* const* d_in, const int* in_sizes, int n_in,
                              void* d_out, int out_size) {
    const float* gts   = (const float*)d_in[0];
    const float* preds = (const float*)d_in[1];
    float* out = (float*)d_out;
    const int B = in_sizes[0] / (N_PTS * 3);

    self_nn_kernel<<<2 * B * NCHNK * S, THR>>>(gts, preds, B);          // 256 blocks
    fused_kernel<<<2 * B + 2 * B * NCHNK * S, THR>>>(gts, preds, B);    // 264 blocks
    combine_kernel<<<B, THR>>>(out);
}